// round 7
// baseline (speedup 1.0000x reference)
#include <cuda_runtime.h>
#include <cuda_bf16.h>
#include <math.h>

// ---------------------------------------------------------------------------
// SCM: out = PWL( eps @ inv(I - A) )
//   eps: [B,16] f32, A: [16,16] f32, p: [16,101] f32, b: [16] f32
// Tables (SoA, 4B stride for full 32-bank LDS spread):
//   w[j][t], c[j][t] with c = delta_bias[spi] - sp*w  ->  out = fma(z, w, c)
// GEMV: packed fp32x2 FMA (FFMA2) vs 64-bit constant words.
// ---------------------------------------------------------------------------

#define NP1 101
#define DIMS 16
#define VMIN_F (-5.0f)
#define INT_LEN_F (10.0f / 99.0f)
#define INV_INT_LEN_F (99.0f / 10.0f)

__device__ float  g_M[DIMS * DIMS];
__device__ float  g_w[DIMS * NP1];
__device__ float  g_c[DIMS * NP1];
__constant__ unsigned long long c_M2[DIMS * 8];

__device__ __forceinline__ unsigned long long ffma2(unsigned long long a,
                                                    unsigned long long b,
                                                    unsigned long long c) {
    unsigned long long d;
    asm("fma.rn.f32x2 %0, %1, %2, %3;" : "=l"(d) : "l"(a), "l"(b), "l"(c));
    return d;
}
__device__ __forceinline__ unsigned long long pack2(float x) {
    unsigned long long d;
    asm("mov.b64 %0, {%1, %1};" : "=l"(d) : "f"(x));
    return d;
}
__device__ __forceinline__ void unpack2(unsigned long long v, float& lo, float& hi) {
    asm("mov.b64 {%0, %1}, %2;" : "=f"(lo), "=f"(hi) : "l"(v));
}

// ---------------------------------------------------------------------------
// Prep: float Gauss-Jordan (warp-parallel pivot) + warp-per-dim PWL tables
// ---------------------------------------------------------------------------
__global__ void prep_kernel(const float* __restrict__ A,
                            const float* __restrict__ p,
                            const float* __restrict__ b) {
    __shared__ float aug[16][33];
    __shared__ float fac[16];
    __shared__ int   s_piv;
    __shared__ float s_w[DIMS][104];
    __shared__ float s_S[DIMS][104];

    const int tid = threadIdx.x;

    {
        int r = tid >> 4, c = tid & 15;
        aug[r][c]      = (r == c ? 1.0f : 0.0f) - A[r * 16 + c];
        aug[r][16 + c] = (r == c ? 1.0f : 0.0f);
    }
    __syncthreads();

    for (int col = 0; col < 16; ++col) {
        if (tid < 32) {
            float v = (tid >= col && tid < 16) ? fabsf(aug[tid][col]) : -1.0f;
            int   ix = tid;
#pragma unroll
            for (int o = 8; o > 0; o >>= 1) {
                float vo = __shfl_down_sync(0xffffffffu, v, o);
                int   io = __shfl_down_sync(0xffffffffu, ix, o);
                if (vo > v) { v = vo; ix = io; }
            }
            if (tid == 0) s_piv = ix;
        }
        __syncthreads();
        const int piv = s_piv;
        if (piv != col && tid < 32) {
            float t = aug[col][tid];
            aug[col][tid] = aug[piv][tid];
            aug[piv][tid] = t;
        }
        __syncthreads();
        if (tid < 32) {
            float pv = aug[col][col];
            __syncwarp();
            aug[col][tid] *= (1.0f / pv);
        }
        if (tid >= 32 && tid < 48) {
            int r = tid - 32;
            fac[r] = (r == col) ? 0.0f : aug[r][col];
        }
        __syncthreads();
#pragma unroll
        for (int it = 0; it < 2; ++it) {
            int id = tid + it * 256;
            int r = id >> 5, j = id & 31;
            aug[r][j] -= fac[r] * aug[col][j];
        }
        __syncthreads();
    }

    {
        int r = tid >> 4, c = tid & 15;
        g_M[r * 16 + c] = aug[r][16 + c];
    }

    const int warp = tid >> 5, lane = tid & 31;
    for (int d = warp; d < DIMS; d += 8) {
        const float* pd = p + d * NP1;
        for (int t = lane; t < NP1; t += 32)
            s_w[d][t] = expf(pd[t]) + 0.001f;
        __syncwarp();

        float pre[4];
        float loc = 0.0f;
#pragma unroll
        for (int q = 0; q < 4; ++q) {
            int i = 4 * lane + q;
            float v = (i < 99) ? (INT_LEN_F * s_w[d][i + 1]) : 0.0f;
            loc += v;
            pre[q] = loc;
        }
        float tot = loc;
#pragma unroll
        for (int o = 1; o < 32; o <<= 1) {
            float t = __shfl_up_sync(0xffffffffu, tot, o);
            if (lane >= o) tot += t;
        }
        float excl = tot - loc;
#pragma unroll
        for (int q = 0; q < 4; ++q) {
            int m = 4 * lane + q;
            if (m <= 99) s_S[d][m] = excl + (q == 0 ? 0.0f : pre[q - 1]);
        }
        __syncwarp();

        const float bd = b[d];
        for (int idx = lane; idx < NP1; idx += 32) {
            int spi = idx > 0 ? idx - 1 : 0;
            float w  = s_w[d][idx];
            float sp = fmaf((float)spi, INT_LEN_F, VMIN_F);
            float db = bd + s_S[d][spi];
            g_w[d * NP1 + idx] = w;
            g_c[d * NP1 + idx] = fmaf(-sp, w, db);
        }
        __syncwarp();
    }
}

// ---------------------------------------------------------------------------
// Main kernel: persistent grid-stride, prefetch next row, SoA table gathers.
// ---------------------------------------------------------------------------
__global__ void __launch_bounds__(256) scm_main_kernel(const float4* __restrict__ eps,
                                                       float4* __restrict__ out,
                                                       int B, int stride) {
    __shared__ float s_w[DIMS * NP1];
    __shared__ float s_c[DIMS * NP1];
    for (int i = threadIdx.x; i < DIMS * NP1; i += 256) {
        s_w[i] = g_w[i];
        s_c[i] = g_c[i];
    }
    __syncthreads();

    int row = blockIdx.x * 256 + threadIdx.x;
    if (row >= B) return;

    const float4* ep = eps + (size_t)row * 4;
    float4 n0 = __ldcs(ep + 0);
    float4 n1 = __ldcs(ep + 1);
    float4 n2 = __ldcs(ep + 2);
    float4 n3 = __ldcs(ep + 3);

    while (true) {
        const float4 e0 = n0, e1 = n1, e2 = n2, e3 = n3;
        const int next = row + stride;

        if (next < B) {
            const float4* np = eps + (size_t)next * 4;
            n0 = __ldcs(np + 0);
            n1 = __ldcs(np + 1);
            n2 = __ldcs(np + 2);
            n3 = __ldcs(np + 3);
        }

        const float e[16] = {e0.x, e0.y, e0.z, e0.w,
                             e1.x, e1.y, e1.z, e1.w,
                             e2.x, e2.y, e2.z, e2.w,
                             e3.x, e3.y, e3.z, e3.w};

        unsigned long long z2[8];
#pragma unroll
        for (int j = 0; j < 8; ++j) z2[j] = 0ULL;

#pragma unroll
        for (int k = 0; k < 16; ++k) {
            const unsigned long long ek2 = pack2(e[k]);
#pragma unroll
            for (int j = 0; j < 8; ++j)
                z2[j] = ffma2(ek2, c_M2[k * 8 + j], z2[j]);
        }

        float o[16];
#pragma unroll
        for (int j2 = 0; j2 < 8; ++j2) {
            float zlo, zhi;
            unpack2(z2[j2], zlo, zhi);
#pragma unroll
            for (int h = 0; h < 2; ++h) {
                const int j = 2 * j2 + h;
                const float zv = h ? zhi : zlo;
                int t = __float2int_rd(fmaf(zv, INV_INT_LEN_F, 49.5f));
                t = min(t, 99);
                t = max(t + 1, 0);
                const int ti = j * NP1 + t;
                o[j] = fmaf(zv, s_w[ti], s_c[ti]);
            }
        }

        float4* op = out + (size_t)row * 4;
        __stcs(op + 0, make_float4(o[0],  o[1],  o[2],  o[3]));
        __stcs(op + 1, make_float4(o[4],  o[5],  o[6],  o[7]));
        __stcs(op + 2, make_float4(o[8],  o[9],  o[10], o[11]));
        __stcs(op + 3, make_float4(o[12], o[13], o[14], o[15]));

        if (next >= B) break;
        row = next;
    }
}

// ---------------------------------------------------------------------------
extern "C" void kernel_launch(void* const* d_in, const int* in_sizes, int n_in,
                              void* d_out, int out_size) {
    const float* eps = nullptr;
    const float* A   = nullptr;
    const float* p   = nullptr;
    const float* b   = nullptr;
    int eps_elems = 0;
    for (int i = 0; i < n_in; ++i) {
        const int sz = in_sizes[i];
        if (sz == 256)       A = (const float*)d_in[i];
        else if (sz == 1616) p = (const float*)d_in[i];
        else if (sz == 16)   b = (const float*)d_in[i];
        else { eps = (const float*)d_in[i]; eps_elems = sz; }
    }
    const int B = eps_elems / 16;

    prep_kernel<<<1, 256>>>(A, p, b);

    void* gM_ptr = nullptr;
    cudaGetSymbolAddress(&gM_ptr, g_M);
    cudaMemcpyToSymbolAsync(c_M2, gM_ptr, DIMS * DIMS * sizeof(float), 0,
                            cudaMemcpyDeviceToDevice);

    int sm_count = 148;
    cudaDeviceGetAttribute(&sm_count, cudaDevAttrMultiProcessorCount, 0);
    int blocks_per_sm = 6;
    cudaOccupancyMaxActiveBlocksPerMultiprocessor(&blocks_per_sm, scm_main_kernel,
                                                  256, 2 * DIMS * NP1 * sizeof(float));
    if (blocks_per_sm < 1) blocks_per_sm = 1;
    const int blocks = sm_count * blocks_per_sm;
    const int stride = blocks * 256;
    scm_main_kernel<<<blocks, 256>>>((const float4*)eps, (float4*)d_out, B, stride);
}

// round 8
// speedup vs baseline: 1.5305x; 1.5305x over previous
#include <cuda_runtime.h>
#include <cuda_bf16.h>
#include <cuda_fp16.h>
#include <math.h>

// ---------------------------------------------------------------------------
// SCM: out = PWL( eps @ inv(I - A) )
//   eps: [B,16] f32, A: [16,16] f32, p: [16,101] f32, b: [16] f32
// Table per (dim, idx): half2{w, c} with c = delta_bias[spi] - sp*w
//   -> out = fma(z, w, c)    (single 4-byte LDS.32 gather per dim)
// GEMV: packed fp32x2 FMA (FFMA2) vs 64-bit constant words.
// ---------------------------------------------------------------------------

#define NP1 101
#define DIMS 16
#define VMIN_F (-5.0f)
#define INT_LEN_F (10.0f / 99.0f)
#define INV_INT_LEN_F (99.0f / 10.0f)

__device__ float    g_M[DIMS * DIMS];
__device__ __half2  g_tab[DIMS * NP1];       // {w, c} in fp16
__constant__ unsigned long long c_M2[DIMS * 8];

__device__ __forceinline__ unsigned long long ffma2(unsigned long long a,
                                                    unsigned long long b,
                                                    unsigned long long c) {
    unsigned long long d;
    asm("fma.rn.f32x2 %0, %1, %2, %3;" : "=l"(d) : "l"(a), "l"(b), "l"(c));
    return d;
}
__device__ __forceinline__ unsigned long long pack2(float x) {
    unsigned long long d;
    asm("mov.b64 %0, {%1, %1};" : "=l"(d) : "f"(x));
    return d;
}
__device__ __forceinline__ void unpack2(unsigned long long v, float& lo, float& hi) {
    asm("mov.b64 {%0, %1}, %2;" : "=f"(lo), "=f"(hi) : "l"(v));
}

// ---------------------------------------------------------------------------
// Prep: float Gauss-Jordan (warp-parallel pivot) + warp-per-dim PWL tables
// ---------------------------------------------------------------------------
__global__ void prep_kernel(const float* __restrict__ A,
                            const float* __restrict__ p,
                            const float* __restrict__ b) {
    __shared__ float aug[16][33];
    __shared__ float fac[16];
    __shared__ int   s_piv;
    __shared__ float s_w[DIMS][104];
    __shared__ float s_S[DIMS][104];

    const int tid = threadIdx.x;

    {
        int r = tid >> 4, c = tid & 15;
        aug[r][c]      = (r == c ? 1.0f : 0.0f) - A[r * 16 + c];
        aug[r][16 + c] = (r == c ? 1.0f : 0.0f);
    }
    __syncthreads();

    for (int col = 0; col < 16; ++col) {
        if (tid < 32) {
            float v = (tid >= col && tid < 16) ? fabsf(aug[tid][col]) : -1.0f;
            int   ix = tid;
#pragma unroll
            for (int o = 8; o > 0; o >>= 1) {
                float vo = __shfl_down_sync(0xffffffffu, v, o);
                int   io = __shfl_down_sync(0xffffffffu, ix, o);
                if (vo > v) { v = vo; ix = io; }
            }
            if (tid == 0) s_piv = ix;
        }
        __syncthreads();
        const int piv = s_piv;
        if (piv != col && tid < 32) {
            float t = aug[col][tid];
            aug[col][tid] = aug[piv][tid];
            aug[piv][tid] = t;
        }
        __syncthreads();
        if (tid < 32) {
            float pv = aug[col][col];
            __syncwarp();
            aug[col][tid] *= (1.0f / pv);
        }
        if (tid >= 32 && tid < 48) {
            int r = tid - 32;
            fac[r] = (r == col) ? 0.0f : aug[r][col];
        }
        __syncthreads();
#pragma unroll
        for (int it = 0; it < 2; ++it) {
            int id = tid + it * 256;
            int r = id >> 5, j = id & 31;
            aug[r][j] -= fac[r] * aug[col][j];
        }
        __syncthreads();
    }

    {
        int r = tid >> 4, c = tid & 15;
        g_M[r * 16 + c] = aug[r][16 + c];
    }

    const int warp = tid >> 5, lane = tid & 31;
    for (int d = warp; d < DIMS; d += 8) {
        const float* pd = p + d * NP1;
        for (int t = lane; t < NP1; t += 32)
            s_w[d][t] = expf(pd[t]) + 0.001f;
        __syncwarp();

        float pre[4];
        float loc = 0.0f;
#pragma unroll
        for (int q = 0; q < 4; ++q) {
            int i = 4 * lane + q;
            float v = (i < 99) ? (INT_LEN_F * s_w[d][i + 1]) : 0.0f;
            loc += v;
            pre[q] = loc;
        }
        float tot = loc;
#pragma unroll
        for (int o = 1; o < 32; o <<= 1) {
            float t = __shfl_up_sync(0xffffffffu, tot, o);
            if (lane >= o) tot += t;
        }
        float excl = tot - loc;
#pragma unroll
        for (int q = 0; q < 4; ++q) {
            int m = 4 * lane + q;
            if (m <= 99) s_S[d][m] = excl + (q == 0 ? 0.0f : pre[q - 1]);
        }
        __syncwarp();

        const float bd = b[d];
        for (int idx = lane; idx < NP1; idx += 32) {
            int spi = idx > 0 ? idx - 1 : 0;
            float w  = s_w[d][idx];
            float sp = fmaf((float)spi, INT_LEN_F, VMIN_F);
            float db = bd + s_S[d][spi];
            float c  = fmaf(-sp, w, db);
            g_tab[d * NP1 + idx] = __floats2half2_rn(w, c);
        }
        __syncwarp();
    }
}

// ---------------------------------------------------------------------------
// Main kernel: persistent grid-stride (simple loop, max occupancy),
// GEMV via FFMA2 + constant memory, PWL via half2 LDS.32 gather.
// ---------------------------------------------------------------------------
__global__ void __launch_bounds__(256) scm_main_kernel(const float4* __restrict__ eps,
                                                       float4* __restrict__ out,
                                                       int B, int stride) {
    __shared__ __half2 s_tab[DIMS * NP1];
    for (int i = threadIdx.x; i < DIMS * NP1; i += 256) s_tab[i] = g_tab[i];
    __syncthreads();

    for (int row = blockIdx.x * 256 + threadIdx.x; row < B; row += stride) {
        const float4* ep = eps + (size_t)row * 4;
        const float4 e0 = __ldcs(ep + 0);
        const float4 e1 = __ldcs(ep + 1);
        const float4 e2 = __ldcs(ep + 2);
        const float4 e3 = __ldcs(ep + 3);

        const float e[16] = {e0.x, e0.y, e0.z, e0.w,
                             e1.x, e1.y, e1.z, e1.w,
                             e2.x, e2.y, e2.z, e2.w,
                             e3.x, e3.y, e3.z, e3.w};

        unsigned long long z2[8];
#pragma unroll
        for (int j = 0; j < 8; ++j) z2[j] = 0ULL;

#pragma unroll
        for (int k = 0; k < 16; ++k) {
            const unsigned long long ek2 = pack2(e[k]);
#pragma unroll
            for (int j = 0; j < 8; ++j)
                z2[j] = ffma2(ek2, c_M2[k * 8 + j], z2[j]);
        }

        float o[16];
#pragma unroll
        for (int j2 = 0; j2 < 8; ++j2) {
            float zlo, zhi;
            unpack2(z2[j2], zlo, zhi);
#pragma unroll
            for (int h = 0; h < 2; ++h) {
                const int j = 2 * j2 + h;
                const float zv = h ? zhi : zlo;
                int t = __float2int_rd(fmaf(zv, INV_INT_LEN_F, 49.5f));
                t = min(t, 99);
                t = max(t + 1, 0);
                const float2 wc = __half22float2(s_tab[j * NP1 + t]);
                o[j] = fmaf(zv, wc.x, wc.y);
            }
        }

        float4* op = out + (size_t)row * 4;
        __stcs(op + 0, make_float4(o[0],  o[1],  o[2],  o[3]));
        __stcs(op + 1, make_float4(o[4],  o[5],  o[6],  o[7]));
        __stcs(op + 2, make_float4(o[8],  o[9],  o[10], o[11]));
        __stcs(op + 3, make_float4(o[12], o[13], o[14], o[15]));
    }
}

// ---------------------------------------------------------------------------
extern "C" void kernel_launch(void* const* d_in, const int* in_sizes, int n_in,
                              void* d_out, int out_size) {
    const float* eps = nullptr;
    const float* A   = nullptr;
    const float* p   = nullptr;
    const float* b   = nullptr;
    int eps_elems = 0;
    for (int i = 0; i < n_in; ++i) {
        const int sz = in_sizes[i];
        if (sz == 256)       A = (const float*)d_in[i];
        else if (sz == 1616) p = (const float*)d_in[i];
        else if (sz == 16)   b = (const float*)d_in[i];
        else { eps = (const float*)d_in[i]; eps_elems = sz; }
    }
    const int B = eps_elems / 16;

    prep_kernel<<<1, 256>>>(A, p, b);

    void* gM_ptr = nullptr;
    cudaGetSymbolAddress(&gM_ptr, g_M);
    cudaMemcpyToSymbolAsync(c_M2, gM_ptr, DIMS * DIMS * sizeof(float), 0,
                            cudaMemcpyDeviceToDevice);

    int sm_count = 148;
    cudaDeviceGetAttribute(&sm_count, cudaDevAttrMultiProcessorCount, 0);
    int blocks_per_sm = 8;
    cudaOccupancyMaxActiveBlocksPerMultiprocessor(&blocks_per_sm, scm_main_kernel,
                                                  256, DIMS * NP1 * sizeof(__half2));
    if (blocks_per_sm < 1) blocks_per_sm = 1;
    const int blocks = sm_count * blocks_per_sm;
    const int stride = blocks * 256;
    scm_main_kernel<<<blocks, 256>>>((const float4*)eps, (float4*)d_out, B, stride);
}

// round 9
// speedup vs baseline: 1.6875x; 1.1026x over previous
#include <cuda_runtime.h>
#include <cuda_bf16.h>
#include <cuda_fp16.h>
#include <math.h>

// ---------------------------------------------------------------------------
// SCM: out = PWL( eps @ inv(I - A) )
//   eps: [B,16] f32, A: [16,16] f32, p: [16,101] f32, b: [16] f32
// Table per (dim, idx): half2{w, c}, c = delta_bias[spi] - sp*w -> out = fma(z,w,c)
// GEMV: packed fp32x2 FMA (FFMA2) vs 64-bit constant words.
// Prep: single sync-free block — warp 16 inverts (I-A) in registers via shuffles,
//       warps 0..15 each build one dim's PWL table concurrently.
// ---------------------------------------------------------------------------

#define NP1 101
#define DIMS 16
#define VMIN_F (-5.0f)
#define INT_LEN_F (10.0f / 99.0f)
#define INV_INT_LEN_F (99.0f / 10.0f)

__device__ float    g_M[DIMS * DIMS];
__device__ __half2  g_tab[DIMS * NP1];
__constant__ unsigned long long c_M2[DIMS * 8];

__device__ __forceinline__ unsigned long long ffma2(unsigned long long a,
                                                    unsigned long long b,
                                                    unsigned long long c) {
    unsigned long long d;
    asm("fma.rn.f32x2 %0, %1, %2, %3;" : "=l"(d) : "l"(a), "l"(b), "l"(c));
    return d;
}
__device__ __forceinline__ unsigned long long pack2(float x) {
    unsigned long long d;
    asm("mov.b64 %0, {%1, %1};" : "=l"(d) : "f"(x));
    return d;
}
__device__ __forceinline__ void unpack2(unsigned long long v, float& lo, float& hi) {
    asm("mov.b64 {%0, %1}, %2;" : "=f"(lo), "=f"(hi) : "l"(v));
}

// ---------------------------------------------------------------------------
// Prep: 1 block, 544 threads (17 warps), NO barriers.
//   warp 16: 16x16 Gauss-Jordan inverse, rows in registers, shuffle-only.
//   warps 0..15: PWL table for dim = warp id, register-only with lane halos.
// ---------------------------------------------------------------------------
__global__ void __launch_bounds__(544) prep_kernel(const float* __restrict__ A,
                                                   const float* __restrict__ p,
                                                   const float* __restrict__ b) {
    const int warp = threadIdx.x >> 5;
    const int lane = threadIdx.x & 31;
    const unsigned FULL = 0xffffffffu;

    if (warp == 16) {
        // ---- one-warp Gauss-Jordan: lane r (<16) owns augmented row r [32] ----
        float a[32];
        const int r = lane;
#pragma unroll
        for (int c = 0; c < 16; ++c) {
            float Av = (r < 16) ? A[r * 16 + c] : 0.0f;
            a[c]      = (r == c ? 1.0f : 0.0f) - Av;
            a[16 + c] = (r == c ? 1.0f : 0.0f);
        }
#pragma unroll
        for (int col = 0; col < 16; ++col) {
            // pivot argmax over lanes in [col,16)
            float v = (lane >= col && lane < 16) ? fabsf(a[col]) : -1.0f;
            int ix = lane;
#pragma unroll
            for (int o = 16; o > 0; o >>= 1) {
                float vo = __shfl_xor_sync(FULL, v, o);
                int   io = __shfl_xor_sync(FULL, ix, o);
                if (vo > v || (vo == v && io < ix)) { v = vo; ix = io; }
            }
            const int piv = ix;
            // swap rows col <-> piv
            const int partner = (lane == col) ? piv : (lane == piv) ? col : lane;
#pragma unroll
            for (int k = 0; k < 32; ++k)
                a[k] = __shfl_sync(FULL, a[k], partner);
            // scale pivot row + eliminate
            const float pv  = __shfl_sync(FULL, a[col], col);
            const float inv = 1.0f / pv;
            const float fac = (lane == col) ? 0.0f : a[col];
#pragma unroll
            for (int k = 0; k < 32; ++k) {
                const float prs = __shfl_sync(FULL, a[k], col) * inv;
                a[k] = (lane == col) ? prs : fmaf(-fac, prs, a[k]);
            }
        }
        if (r < 16) {
#pragma unroll
            for (int c = 0; c < 16; ++c)
                g_M[r * 16 + c] = a[16 + c];
        }
    } else {
        // ---- warp per dim: PWL table, register-only ----
        const int d = warp;
        const float* pd = p + d * NP1;

        // lane owns entries i0..i0+3 (i0 = 4*lane); lanes 0..24 active, lane 25 holds idx 100
        float wl[4];
#pragma unroll
        for (int q = 0; q < 4; ++q) {
            const int i = 4 * lane + q;
            wl[q] = (i < NP1) ? (expf(pd[i]) + 0.001f) : 0.0f;
        }
        // neighbor halo: w(4*lane+4) = next lane's wl[0]
        const float w_next0 = __shfl_down_sync(FULL, wl[0], 1);

        // delta_h[i] = INT_LEN * w[i+1], i = 0..98 ; inclusive within-lane prefix
        float pre[4];
        float loc = 0.0f;
#pragma unroll
        for (int q = 0; q < 4; ++q) {
            const int i = 4 * lane + q;
            const float wip1 = (q < 3) ? wl[q + 1] : w_next0;
            const float v = (i < 99) ? (INT_LEN_F * wip1) : 0.0f;
            loc += v;
            pre[q] = loc;
        }
        // warp-inclusive scan of lane totals
        float tot = loc;
#pragma unroll
        for (int o = 1; o < 32; o <<= 1) {
            const float t = __shfl_up_sync(FULL, tot, o);
            if (lane >= o) tot += t;
        }
        const float excl = tot - loc;            // S(4*lane)
        // S(m) for m = 4*lane + q
        float S[4];
#pragma unroll
        for (int q = 0; q < 4; ++q)
            S[q] = excl + (q == 0 ? 0.0f : pre[q - 1]);
        // halo: S(4*lane - 1) = prev lane's S[3]
        const float S_prevlast = __shfl_up_sync(FULL, S[3], 1);

        const float bd = b[d];
#pragma unroll
        for (int q = 0; q < 4; ++q) {
            const int idx = 4 * lane + q;
            if (idx < NP1) {
                const int   spi = idx > 0 ? idx - 1 : 0;
                const float Ssp = (idx == 0) ? 0.0f
                                : (q == 0)   ? S_prevlast
                                             : S[q - 1];
                const float w  = wl[q];
                const float sp = fmaf((float)spi, INT_LEN_F, VMIN_F);
                const float db = bd + Ssp;
                g_tab[d * NP1 + idx] = __floats2half2_rn(w, fmaf(-sp, w, db));
            }
        }
    }
}

// ---------------------------------------------------------------------------
// Main kernel: persistent grid-stride; GEMV via FFMA2 + constant memory;
// epilogue batched: all 16 indices -> all 16 LDS.32 gathers -> convert/FMA/store.
// ---------------------------------------------------------------------------
__global__ void __launch_bounds__(256, 6) scm_main_kernel(const float4* __restrict__ eps,
                                                          float4* __restrict__ out,
                                                          int B, int stride) {
    __shared__ __half2 s_tab[DIMS * NP1];
    for (int i = threadIdx.x; i < DIMS * NP1; i += 256) s_tab[i] = g_tab[i];
    __syncthreads();

    for (int row = blockIdx.x * 256 + threadIdx.x; row < B; row += stride) {
        const float4* ep = eps + (size_t)row * 4;
        const float4 e0 = __ldcs(ep + 0);
        const float4 e1 = __ldcs(ep + 1);
        const float4 e2 = __ldcs(ep + 2);
        const float4 e3 = __ldcs(ep + 3);

        const float e[16] = {e0.x, e0.y, e0.z, e0.w,
                             e1.x, e1.y, e1.z, e1.w,
                             e2.x, e2.y, e2.z, e2.w,
                             e3.x, e3.y, e3.z, e3.w};

        unsigned long long z2[8];
#pragma unroll
        for (int j = 0; j < 8; ++j) z2[j] = 0ULL;

#pragma unroll
        for (int k = 0; k < 16; ++k) {
            const unsigned long long ek2 = pack2(e[k]);
#pragma unroll
            for (int j = 0; j < 8; ++j)
                z2[j] = ffma2(ek2, c_M2[k * 8 + j], z2[j]);
        }

        // unpack z, compute all indices
        float zv[16];
#pragma unroll
        for (int j2 = 0; j2 < 8; ++j2)
            unpack2(z2[j2], zv[2 * j2], zv[2 * j2 + 1]);

        int ti[16];
#pragma unroll
        for (int j = 0; j < 16; ++j) {
            int t = __float2int_rd(fmaf(zv[j], INV_INT_LEN_F, 49.5f));
            t = min(t, 99);
            t = max(t + 1, 0);
            ti[j] = j * NP1 + t;
        }

        // batched gathers (independent LDS.32s, latencies overlap)
        __half2 u[16];
#pragma unroll
        for (int j = 0; j < 16; ++j) u[j] = s_tab[ti[j]];

        float o[16];
#pragma unroll
        for (int j = 0; j < 16; ++j) {
            const float2 wc = __half22float2(u[j]);
            o[j] = fmaf(zv[j], wc.x, wc.y);
        }

        float4* op = out + (size_t)row * 4;
        __stcs(op + 0, make_float4(o[0],  o[1],  o[2],  o[3]));
        __stcs(op + 1, make_float4(o[4],  o[5],  o[6],  o[7]));
        __stcs(op + 2, make_float4(o[8],  o[9],  o[10], o[11]));
        __stcs(op + 3, make_float4(o[12], o[13], o[14], o[15]));
    }
}

// ---------------------------------------------------------------------------
extern "C" void kernel_launch(void* const* d_in, const int* in_sizes, int n_in,
                              void* d_out, int out_size) {
    const float* eps = nullptr;
    const float* A   = nullptr;
    const float* p   = nullptr;
    const float* b   = nullptr;
    int eps_elems = 0;
    for (int i = 0; i < n_in; ++i) {
        const int sz = in_sizes[i];
        if (sz == 256)       A = (const float*)d_in[i];
        else if (sz == 1616) p = (const float*)d_in[i];
        else if (sz == 16)   b = (const float*)d_in[i];
        else { eps = (const float*)d_in[i]; eps_elems = sz; }
    }
    const int B = eps_elems / 16;

    prep_kernel<<<1, 544>>>(A, p, b);

    void* gM_ptr = nullptr;
    cudaGetSymbolAddress(&gM_ptr, g_M);
    cudaMemcpyToSymbolAsync(c_M2, gM_ptr, DIMS * DIMS * sizeof(float), 0,
                            cudaMemcpyDeviceToDevice);

    int sm_count = 148;
    cudaDeviceGetAttribute(&sm_count, cudaDevAttrMultiProcessorCount, 0);
    int blocks_per_sm = 6;
    cudaOccupancyMaxActiveBlocksPerMultiprocessor(&blocks_per_sm, scm_main_kernel,
                                                  256, DIMS * NP1 * sizeof(__half2));
    if (blocks_per_sm < 1) blocks_per_sm = 1;
    const int blocks = sm_count * blocks_per_sm;
    const int stride = blocks * 256;
    scm_main_kernel<<<blocks, 256>>>((const float4*)eps, (float4*)d_out, B, stride);
}